// round 6
// baseline (speedup 1.0000x reference)
#include <cuda_runtime.h>
#include <cuda_bf16.h>

#define N_NODES   150000
#define N_EDGES   2400000
#define N_FEAT    32
#define N_GRAPHS  8192
#define H1        32
#define H2        64
#define BN_EPS    1e-5f
#define N_SBLK    ((N_NODES + 255) / 256)   // 586 scan blocks

// ---------------- scratch (static device allocations: allowed) ----------------
__device__ int   d_flag32;              // 1 if edge_index/batch are int32, 0 if int64
__device__ int   d_ideg[N_NODES];       // in-degree (without self loop)
__device__ float d_isq[N_NODES];
__device__ int   d_batch[N_NODES];
__device__ int   d_rowstart[N_NODES];   // CSR row starts (exclusive scan of ideg)
__device__ int   d_cursor[N_NODES];     // placement cursors
__device__ int   d_bsum[1024];          // scan block sums
__device__ int   d_boff[1024];          // scan block offsets
__device__ int   d_csr[N_EDGES];        // src ids bucketed by dst
__device__ __align__(16) int2  d_edge[N_EDGES];       // packed (src, dst) int32
__device__ __align__(16) float d_h1s[N_NODES * H1];   // (x@W1) * isq[row]
__device__ __align__(16) float d_acc1[N_NODES * H1];  // conv1 result
__device__ __align__(16) float d_zs[N_NODES * H1];    // relu(BN(h1)) * isq
__device__ float d_stats[64];           // [0:32) sum, [32:64) sumsq of BN input
__device__ float d_A[H1];               // rstd*gamma
__device__ float d_C[H1];               // (b1-mean)*A + beta
__device__ __align__(16) float d_poolz[N_GRAPHS * H1];  // 32-dim pooled pre-W2 sums
__device__ float d_cnt[N_GRAPHS];

// ---------------- kernels ----------------

// Detect index dtype (int32 vs int64) from value range.
__global__ void k_detect(const long long* __restrict__ ei) {
    if (blockIdx.x == 0 && threadIdx.x == 0) {
        int bad = 0;
        for (int i = 0; i < 64; i++) {
            long long v = ei[i];
            if (v < 0 || v >= (long long)N_NODES) bad = 1;
        }
        d_flag32 = bad;
    }
}

__global__ void k_init() {
    int i = blockIdx.x * blockDim.x + threadIdx.x;
    if (i < N_NODES)          d_ideg[i] = 0;
    if (i < N_GRAPHS * H1)    d_poolz[i] = 0.0f;
    if (i < N_GRAPHS)         d_cnt[i] = 0.0f;
    if (i < 64)               d_stats[i] = 0.0f;
}

// edge conversion to packed int32 + int degree histogram (by dst)
__global__ void k_deg(const void* __restrict__ ei) {
    int e = blockIdx.x * blockDim.x + threadIdx.x;
    if (e < N_EDGES) {
        int s, d;
        if (d_flag32) {
            const int* p = (const int*)ei;
            s = p[e]; d = p[N_EDGES + e];
        } else {
            const long long* p = (const long long*)ei;
            s = (int)p[e]; d = (int)p[N_EDGES + e];
        }
        d_edge[e] = make_int2(s, d);
        atomicAdd(&d_ideg[d], 1);
    }
}

// ---- prefix scan of d_ideg -> d_rowstart (exclusive) ----
__global__ void k_scanA() {
    __shared__ int sh[256];
    int i = blockIdx.x * 256 + threadIdx.x;
    sh[threadIdx.x] = (i < N_NODES) ? d_ideg[i] : 0;
    __syncthreads();
#pragma unroll
    for (int off = 128; off > 0; off >>= 1) {
        if (threadIdx.x < off) sh[threadIdx.x] += sh[threadIdx.x + off];
        __syncthreads();
    }
    if (threadIdx.x == 0) d_bsum[blockIdx.x] = sh[0];
}

__global__ void k_scanB() {   // single block of 1024, scans N_SBLK block sums
    __shared__ int sh[1024];
    int t = threadIdx.x;
    int v = (t < N_SBLK) ? d_bsum[t] : 0;
    sh[t] = v;
    __syncthreads();
#pragma unroll
    for (int off = 1; off < 1024; off <<= 1) {
        int a = (t >= off) ? sh[t - off] : 0;
        __syncthreads();
        sh[t] += a;
        __syncthreads();
    }
    if (t < N_SBLK) d_boff[t] = sh[t] - v;   // exclusive
}

__global__ void k_scanC() {
    __shared__ int sh[256];
    int t = threadIdx.x;
    int i = blockIdx.x * 256 + t;
    int v = (i < N_NODES) ? d_ideg[i] : 0;
    sh[t] = v;
    __syncthreads();
#pragma unroll
    for (int off = 1; off < 256; off <<= 1) {
        int a = (t >= off) ? sh[t - off] : 0;
        __syncthreads();
        sh[t] += a;
        __syncthreads();
    }
    if (i < N_NODES) {
        int ex = sh[t] - v + d_boff[blockIdx.x];
        d_rowstart[i] = ex;
        d_cursor[i]   = ex;
    }
}

// bucket src ids by dst
__global__ void k_place() {
    int e = blockIdx.x * blockDim.x + threadIdx.x;
    if (e < N_EDGES) {
        int2 ed = d_edge[e];
        int pos = atomicAdd(&d_cursor[ed.y], 1);
        d_csr[pos] = ed.x;
    }
}

// isq (self loop -> deg+1) + batch conversion + per-graph counts
__global__ void k_isq(const void* __restrict__ batch) {
    int i = blockIdx.x * blockDim.x + threadIdx.x;
    if (i < N_NODES) {
        d_isq[i] = rsqrtf((float)(d_ideg[i] + 1));
        int b = d_flag32 ? ((const int*)batch)[i]
                         : (int)((const long long*)batch)[i];
        d_batch[i] = b;
        atomicAdd(&d_cnt[b], 1.0f);
    }
}

// h1s = (x @ W1) * isq
__global__ void k_gemm1(const float* __restrict__ x, const float* __restrict__ W1) {
    __shared__ float sW[H1 * H1];
    int tid = threadIdx.x;
    for (int i = tid; i < H1 * H1; i += 256) sW[i] = W1[i];
    __syncthreads();
    int warp = tid >> 5, lane = tid & 31;
    int r = blockIdx.x * 8 + warp;
    if (r >= N_NODES) return;
    float xv = x[r * N_FEAT + lane];
    float acc = 0.f;
#pragma unroll
    for (int k = 0; k < 32; k++) {
        float xk = __shfl_sync(0xffffffffu, xv, k);
        acc += xk * sW[k * H1 + lane];
    }
    d_h1s[r * H1 + lane] = acc * d_isq[r];
}

// conv1: warp per dst node, lane = feature, CSR segment reduce, no atomics.
__global__ void k_conv1() {
    int gw = (blockIdx.x * blockDim.x + threadIdx.x) >> 5;
    int lane = threadIdx.x & 31;
    if (gw >= N_NODES) return;
    int start = d_rowstart[gw];
    int deg   = d_ideg[gw];
    float acc = d_h1s[gw * H1 + lane];   // self loop seed
    for (int base = 0; base < deg; base += 32) {
        int n = deg - base; if (n > 32) n = 32;
        int s = (lane < n) ? d_csr[start + base + lane] : 0;
#pragma unroll 4
        for (int j = 0; j < n; j++) {
            int sj = __shfl_sync(0xffffffffu, s, j);
            acc += __ldg(&d_h1s[sj * H1 + lane]);
        }
    }
    d_acc1[gw * H1 + lane] = acc;
}

// BN stats over y = acc1*isq + b1 (per feature sum, sumsq)
__global__ void k_bnstats(const float* __restrict__ b1) {
    __shared__ float s_sum[256], s_sq[256];
    int tid = threadIdx.x;
    int f = tid & 31;
    float bf = __ldg(&b1[f]);
    float ls = 0.f, lq = 0.f;
    int stride = gridDim.x * blockDim.x;
    for (int i = blockIdx.x * blockDim.x + tid; i < N_NODES * H1; i += stride) {
        int row = i >> 5;
        float y = d_acc1[i] * d_isq[row] + bf;
        ls += y;
        lq += y * y;
    }
    s_sum[tid] = ls; s_sq[tid] = lq;
    __syncthreads();
    if (tid < 32) {
        float ts = s_sum[tid], tq = s_sq[tid];
#pragma unroll
        for (int g = 1; g < 8; g++) { ts += s_sum[tid + 32 * g]; tq += s_sq[tid + 32 * g]; }
        atomicAdd(&d_stats[tid], ts);
        atomicAdd(&d_stats[32 + tid], tq);
    }
}

__global__ void k_bnfinal(const float* __restrict__ b1,
                          const float* __restrict__ gamma,
                          const float* __restrict__ beta) {
    int f = threadIdx.x;
    float n = (float)N_NODES;
    float mean = d_stats[f] / n;
    float var = d_stats[32 + f] / n - mean * mean;
    float A = rsqrtf(var + BN_EPS) * gamma[f];
    d_A[f] = A;
    d_C[f] = (b1[f] - mean) * A + beta[f];
}

// zs = relu(acc1*isq*A + C) * isq
__global__ void k_zs() {
    int i = blockIdx.x * blockDim.x + threadIdx.x;
    if (i >= N_NODES * H1) return;
    int row = i >> 5, f = i & 31;
    float isq = d_isq[row];
    float z = fmaxf(d_acc1[i] * isq * d_A[f] + d_C[f], 0.0f);
    d_zs[i] = z * isq;
}

// conv2 + pool fused: warp per dst node, result stays in registers,
// scaled by isq and reduced straight into poolz[batch[node]].
__global__ void k_conv2pool() {
    int gw = (blockIdx.x * blockDim.x + threadIdx.x) >> 5;
    int lane = threadIdx.x & 31;
    if (gw >= N_NODES) return;
    int start = d_rowstart[gw];
    int deg   = d_ideg[gw];
    float acc = d_zs[gw * H1 + lane];    // self loop seed
    for (int base = 0; base < deg; base += 32) {
        int n = deg - base; if (n > 32) n = 32;
        int s = (lane < n) ? d_csr[start + base + lane] : 0;
#pragma unroll 4
        for (int j = 0; j < n; j++) {
            int sj = __shfl_sync(0xffffffffu, s, j);
            acc += __ldg(&d_zs[sj * H1 + lane]);
        }
    }
    float v = acc * d_isq[gw];
    int b = d_batch[gw];
    atomicAdd(&d_poolz[b * H1 + lane], v);   // RED (no return)
}

// warp-per-graph head: g64 = (poolz@W2 + cnt*b2)/max(cnt,1); relu(g@Wfc1+bfc1); @Wfc2+bfc2
__global__ void __launch_bounds__(1024) k_mlp(const float* __restrict__ W2,
                                              const float* __restrict__ b2,
                                              const float* __restrict__ Wfc1,
                                              const float* __restrict__ bfc1,
                                              const float* __restrict__ Wfc2,
                                              const float* __restrict__ bfc2,
                                              float* __restrict__ out) {
    __shared__ float sW2[H1 * H2];
    __shared__ float sW1[64 * 128];
    __shared__ float sb1[128];
    __shared__ float sb2[64];
    int tid = threadIdx.x;
    for (int i = tid; i < H1 * H2; i += 1024) sW2[i] = W2[i];
    for (int i = tid; i < 64 * 128; i += 1024) sW1[i] = Wfc1[i];
    if (tid < 128) sb1[tid] = bfc1[tid];
    if (tid < 64)  sb2[tid] = b2[tid];
    __syncthreads();
    int warp = tid >> 5, lane = tid & 31;
    int g = blockIdx.x * 32 + warp;
    float cnt = d_cnt[g];
    float inv = 1.0f / fmaxf(cnt, 1.0f);
    float p = d_poolz[g * H1 + lane];
    float e0 = 0.f, e1 = 0.f;
#pragma unroll
    for (int k = 0; k < 32; k++) {
        float pk = __shfl_sync(0xffffffffu, p, k);
        e0 += pk * sW2[k * H2 + lane];
        e1 += pk * sW2[k * H2 + lane + 32];
    }
    float g0 = (e0 + cnt * sb2[lane]) * inv;
    float g1 = (e1 + cnt * sb2[lane + 32]) * inv;

    float a0 = 0.f, a1 = 0.f, a2 = 0.f, a3 = 0.f;
#pragma unroll
    for (int k = 0; k < 32; k++) {
        float gk = __shfl_sync(0xffffffffu, g0, k);
        const float* w = &sW1[k * 128];
        a0 += gk * w[lane]; a1 += gk * w[lane + 32]; a2 += gk * w[lane + 64]; a3 += gk * w[lane + 96];
    }
#pragma unroll
    for (int k = 0; k < 32; k++) {
        float gk = __shfl_sync(0xffffffffu, g1, k);
        const float* w = &sW1[(k + 32) * 128];
        a0 += gk * w[lane]; a1 += gk * w[lane + 32]; a2 += gk * w[lane + 64]; a3 += gk * w[lane + 96];
    }
    float h0 = fmaxf(a0 + sb1[lane], 0.f);
    float h1 = fmaxf(a1 + sb1[lane + 32], 0.f);
    float h2 = fmaxf(a2 + sb1[lane + 64], 0.f);
    float h3 = fmaxf(a3 + sb1[lane + 96], 0.f);

    float o0 = __ldg(&bfc2[lane]);
    float o1 = __ldg(&bfc2[lane + 32]);
    float o2 = __ldg(&bfc2[lane + 64]);
    float o3 = __ldg(&bfc2[lane + 96]);
#pragma unroll
    for (int k = 0; k < 32; k++) {
        float hk = __shfl_sync(0xffffffffu, h0, k);
        const float* w = &Wfc2[k * 128];
        o0 += hk * __ldg(&w[lane]); o1 += hk * __ldg(&w[lane + 32]);
        o2 += hk * __ldg(&w[lane + 64]); o3 += hk * __ldg(&w[lane + 96]);
    }
#pragma unroll
    for (int k = 0; k < 32; k++) {
        float hk = __shfl_sync(0xffffffffu, h1, k);
        const float* w = &Wfc2[(k + 32) * 128];
        o0 += hk * __ldg(&w[lane]); o1 += hk * __ldg(&w[lane + 32]);
        o2 += hk * __ldg(&w[lane + 64]); o3 += hk * __ldg(&w[lane + 96]);
    }
#pragma unroll
    for (int k = 0; k < 32; k++) {
        float hk = __shfl_sync(0xffffffffu, h2, k);
        const float* w = &Wfc2[(k + 64) * 128];
        o0 += hk * __ldg(&w[lane]); o1 += hk * __ldg(&w[lane + 32]);
        o2 += hk * __ldg(&w[lane + 64]); o3 += hk * __ldg(&w[lane + 96]);
    }
#pragma unroll
    for (int k = 0; k < 32; k++) {
        float hk = __shfl_sync(0xffffffffu, h3, k);
        const float* w = &Wfc2[(k + 96) * 128];
        o0 += hk * __ldg(&w[lane]); o1 += hk * __ldg(&w[lane + 32]);
        o2 += hk * __ldg(&w[lane + 64]); o3 += hk * __ldg(&w[lane + 96]);
    }
    out[g * 64 + lane]                      = o0;
    out[g * 64 + lane + 32]                 = o1;
    out[N_GRAPHS * 64 + g * 64 + lane]      = o2;
    out[N_GRAPHS * 64 + g * 64 + lane + 32] = o3;
}

// ---------------- launch ----------------
extern "C" void kernel_launch(void* const* d_in, const int* in_sizes, int n_in,
                              void* d_out, int out_size) {
    const float* x     = (const float*)d_in[0];
    const void*  ei    = d_in[1];
    const void*  batch = d_in[2];
    const float* W1    = (const float*)d_in[3];
    const float* b1    = (const float*)d_in[4];
    const float* gamma = (const float*)d_in[5];
    const float* beta  = (const float*)d_in[6];
    const float* W2    = (const float*)d_in[7];
    const float* b2    = (const float*)d_in[8];
    const float* Wfc1  = (const float*)d_in[9];
    const float* bfc1  = (const float*)d_in[10];
    const float* Wfc2  = (const float*)d_in[11];
    const float* bfc2  = (const float*)d_in[12];
    float* out = (float*)d_out;

    k_detect<<<1, 32>>>((const long long*)ei);
    k_init<<<(N_GRAPHS * H1 + 255) / 256, 256>>>();
    k_deg<<<(N_EDGES + 255) / 256, 256>>>(ei);
    k_scanA<<<N_SBLK, 256>>>();
    k_scanB<<<1, 1024>>>();
    k_scanC<<<N_SBLK, 256>>>();
    k_place<<<(N_EDGES + 255) / 256, 256>>>();
    k_isq<<<(N_NODES + 255) / 256, 256>>>(batch);
    k_gemm1<<<(N_NODES + 7) / 8, 256>>>(x, W1);
    k_conv1<<<(N_NODES + 7) / 8, 256>>>();
    k_bnstats<<<1024, 256>>>(b1);
    k_bnfinal<<<1, 32>>>(b1, gamma, beta);
    k_zs<<<(N_NODES * H1 + 255) / 256, 256>>>();
    k_conv2pool<<<(N_NODES + 7) / 8, 256>>>();
    k_mlp<<<N_GRAPHS / 32, 1024>>>(W2, b2, Wfc1, bfc1, Wfc2, bfc2, out);
}